// round 6
// baseline (speedup 1.0000x reference)
#include <cuda_runtime.h>

#define THREADS 256
#define LEAK 0.05f

// folded per-channel linear tail
__device__ float g_Wfold[32 * 64];
__device__ float g_bfold[64];
// Winograd F(4,3)-transformed conv2 weights: [8ic][6j][4ocq][64c][4ocm]
__device__ __align__(16) float g_W6[8 * 6 * 4 * 64 * 4];

// ---------------------------------------------------------------------------
// packed f32x2 helpers
// ---------------------------------------------------------------------------
typedef unsigned long long ull;
__device__ __forceinline__ ull pack2(float lo, float hi) {
    ull d; asm("mov.b64 %0, {%1, %2};" : "=l"(d) : "f"(lo), "f"(hi)); return d;
}
__device__ __forceinline__ ull dup2(float v) {
    ull d; asm("mov.b64 %0, {%1, %1};" : "=l"(d) : "f"(v)); return d;
}
__device__ __forceinline__ void ffma2(ull& acc, ull a, ull b) {
    asm("fma.rn.f32x2 %0, %1, %2, %0;" : "+l"(acc) : "l"(a), "l"(b));
}
__device__ __forceinline__ ull ffma2_3(ull a, ull b, ull c) {
    ull d; asm("fma.rn.f32x2 %0, %1, %2, %3;" : "=l"(d) : "l"(a), "l"(b), "l"(c)); return d;
}
__device__ __forceinline__ ull add2(ull a, ull b) {
    ull d; asm("add.rn.f32x2 %0, %1, %2;" : "=l"(d) : "l"(a), "l"(b)); return d;
}
__device__ __forceinline__ void unpack2(float& lo, float& hi, ull v) {
    asm("mov.b64 {%0, %1}, %2;" : "=f"(lo), "=f"(hi) : "l"(v));
}

// ---------------------------------------------------------------------------
// Prep 1: collapse the (purely linear) FC stack + detection head.
// ---------------------------------------------------------------------------
__global__ void prep_kernel(const float* __restrict__ fw1, const float* __restrict__ fb1,
                            const float* __restrict__ fw2, const float* __restrict__ fb2,
                            const float* __restrict__ fw3, const float* __restrict__ fb3,
                            const float* __restrict__ dw1, const float* __restrict__ db1,
                            const float* __restrict__ dw2, const float* __restrict__ db2)
{
    int c = blockIdx.x, t = threadIdx.x;
    __shared__ float u[64];
    __shared__ float t1[32];

    float s = 0.f;
    #pragma unroll 4
    for (int j = 0; j < 32; j++)
        s += fw3[c * 32 + j] * fw2[(c * 32 + j) * 64 + t];
    u[t] = s;

    if (t < 32) {
        float a = fb2[c * 32 + t];
        #pragma unroll 4
        for (int i = 0; i < 64; i++)
            a += fw2[(c * 32 + t) * 64 + i] * fb1[c * 64 + i];
        t1[t] = a;
    }
    __syncthreads();

    float gc = 0.f;
    #pragma unroll 4
    for (int j = 0; j < 32; j++) gc += dw2[j] * dw1[j * 64 + c];

    if (t < 32) {
        float wv = 0.f;
        #pragma unroll 4
        for (int i = 0; i < 64; i++)
            wv += u[i] * fw1[(c * 64 + i) * 32 + t];
        g_Wfold[t * 64 + c] = gc * wv;
    }
    if (t == 0) {
        float bias = fb3[c];
        for (int j = 0; j < 32; j++) bias += fw3[c * 32 + j] * t1[j];
        float C = db2[0];
        for (int j = 0; j < 32; j++) C += dw2[j] * db1[j];
        g_bfold[c] = gc * bias + C * (1.0f / 64.0f);
    }
}

// ---------------------------------------------------------------------------
// Prep 2: Winograd F(4,3) weight transform  w6[j] = G[j] . (w0,w1,w2)
//   G = [ 1/4 0 0; -1/6 -1/6 -1/6; -1/6 1/6 -1/6;
//         1/24 1/12 1/6; 1/24 -1/12 1/6; 0 0 1 ]
// g_W6 layout: idx = ic*6144 + j*1024 + ocq*256 + c*4 + jm  (oc = ocq*4+jm)
// ---------------------------------------------------------------------------
__global__ void prep_w6_kernel(const float* __restrict__ w2)
{
    int idx = blockIdx.x * 256 + threadIdx.x;   // 0..49151
    int jm  = idx & 3;
    int c   = (idx >> 2) & 63;
    int ocq = (idx >> 8) & 3;
    int rem = idx >> 10;
    int j   = rem % 6;
    int ic  = rem / 6;
    int oc  = ocq * 4 + jm;
    const float* wp = w2 + ((c * 16 + oc) * 8 + ic) * 3;
    float w0 = wp[0], w1 = wp[1], w2v = wp[2];
    float r;
    const float S6 = 1.0f / 6.0f, S24 = 1.0f / 24.0f, S12 = 1.0f / 12.0f;
    switch (j) {
        case 0: r = 0.25f * w0; break;
        case 1: r = -S6 * (w0 + w1 + w2v); break;
        case 2: r = -S6 * w0 + S6 * w1 - S6 * w2v; break;
        case 3: r = S24 * w0 + S12 * w1 + S6 * w2v; break;
        case 4: r = S24 * w0 - S12 * w1 + S6 * w2v; break;
        default: r = w2v; break;
    }
    g_W6[idx] = r;
}

// ---------------------------------------------------------------------------
// Main: conv1 + pool/leaky as before; conv2 via Winograd F(4,3):
//   u = BT . m  (per ic, sample-packed);  acc6[j] += w6[ic][j][oc] * u[j]
//   y = AT . acc6 + bias;  then pool/leaky + folded 32-dot + reduction.
// Shared float layout:
//   sW6  [8][6][4][64][4] @0       (49152)
//   sW1q [8][64][4]       @49152   (2048)
//   sB2q [4][64][4]       @51200   (1024)
//   sWFq [16][64][2]      @52224   (2048)
//   sBF  [64]             @54272
//   sRED [2][16]          @54336
// ---------------------------------------------------------------------------
#define SM_FLOATS 54368

__global__ __launch_bounds__(THREADS, 1)
void main_kernel(const float* __restrict__ x,
                 const float* __restrict__ w1, const float* __restrict__ b1,
                 const float* __restrict__ b2,
                 float* __restrict__ out, int B)
{
    extern __shared__ float sm[];
    float* sW6  = sm;
    float* sW1q = sm + 49152;
    float* sB2q = sm + 51200;
    float* sWFq = sm + 52224;
    float* sBF  = sm + 54272;
    float* sRED = sm + 54336;

    const int tid = threadIdx.x;

    // ---- stage (one-time) ----
    {
        const float4* src = reinterpret_cast<const float4*>(g_W6);
        float4* dst = reinterpret_cast<float4*>(sW6);
        for (int i = tid; i < 12288; i += THREADS) dst[i] = src[i];
    }
    for (int i = tid; i < 2048; i += THREADS) {
        int o = i >> 8, c = (i >> 2) & 63, j = i & 3;
        sW1q[i] = (j < 3) ? w1[c * 24 + o * 3 + j] : b1[c * 8 + o];
    }
    for (int i = tid; i < 1024; i += THREADS) {
        int ocq = i >> 8, c = (i >> 2) & 63, j = i & 3;
        sB2q[i] = b2[c * 16 + ocq * 4 + j];
    }
    for (int i = tid; i < 2048; i += THREADS) {
        int oc = i >> 7, c = (i >> 1) & 63, q = i & 1;
        sWFq[i] = g_Wfold[(oc * 2 + q) * 64 + c];
    }
    for (int i = tid; i < 64; i += THREADS) sBF[i] = g_bfold[i];
    __syncthreads();

    const int c = tid & 63;
    const int g = tid >> 6;
    const int w = tid >> 5;
    const int NG = B >> 3;

    const float bfc = sBF[c];
    // packed constants for the transforms
    const ull c2p  = dup2(2.0f);
    const ull cm2p = dup2(-2.0f);
    const ull c4p  = dup2(4.0f);
    const ull cm4p = dup2(-4.0f);
    const ull c8p  = dup2(8.0f);
    const ull cm1p = dup2(-1.0f);
    // sub2(a,b) = fma2(-1, b, a)
    #define SUB2(a, b) ffma2_3(cm1p, (b), (a))

    for (int grp = blockIdx.x; grp < NG; grp += gridDim.x) {
        const float* xp0 = x + (size_t)(grp * 8 + g) * 1024 + c;
        const float* xp1 = xp0 + 4 * 1024;

        ull xr[14];
        #pragma unroll
        for (int t = 0; t < 14; t++) xr[t] = pack2(xp0[t * 64], xp1[t * 64]);

        // acc6[s][ocq][h][j], zero-init (bias added in output transform)
        ull acc[2][4][2][6];
        #pragma unroll
        for (int s = 0; s < 2; s++)
            #pragma unroll
            for (int ocq = 0; ocq < 4; ocq++)
                #pragma unroll
                for (int h = 0; h < 2; h++)
                    #pragma unroll
                    for (int j = 0; j < 6; j++) acc[s][ocq][h][j] = 0ull;

        #pragma unroll 1
        for (int ic = 0; ic < 8; ic++) {
            const float4 wv1 = *reinterpret_cast<const float4*>(&sW1q[(ic << 8) + (c << 2)]);
            const ull wa2 = dup2(wv1.x);
            const ull wb2 = dup2(wv1.y);
            const ull wc2 = dup2(wv1.z);
            const ull bb2 = dup2(wv1.w);

            // conv1 (sample-packed) + pool + leaky -> m[0..5] sample-packed
            ull m[6];
            #pragma unroll
            for (int q = 0; q < 6; q++) {
                ull h0 = ffma2_3(wa2, xr[2 * q],
                         ffma2_3(wb2, xr[2 * q + 1],
                         ffma2_3(wc2, xr[2 * q + 2], bb2)));
                ull h1 = ffma2_3(wa2, xr[2 * q + 1],
                         ffma2_3(wb2, xr[2 * q + 2],
                         ffma2_3(wc2, xr[2 * q + 3], bb2)));
                float a0, a1, b0, b1;
                unpack2(a0, a1, h0);
                unpack2(b0, b1, h1);
                float M0 = fmaxf(a0, b0), M1 = fmaxf(a1, b1);
                m[q] = pack2(fmaxf(M0, LEAK * M0), fmaxf(M1, LEAK * M1));
            }

            // input transform u = BT m (sample-packed)
            ull E  = SUB2(m[4], m[2]);
            ull F  = SUB2(m[3], m[1]);
            ull A  = add2(m[1], m[2]);
            ull C0 = add2(m[3], m[4]);
            ull u[6];
            u[0] = ffma2_3(c4p,  SUB2(m[0], m[2]), E);
            u[1] = ffma2_3(cm4p, A, C0);
            u[2] = ffma2_3(c4p,  SUB2(m[1], m[2]), SUB2(m[4], m[3]));
            u[3] = ffma2_3(c2p,  F, E);
            u[4] = ffma2_3(cm2p, F, E);
            u[5] = ffma2_3(c4p,  SUB2(m[1], m[3]), SUB2(m[5], m[3]));

            // MAC in transform space (acc packed over oc-pairs)
            const float* wbase = sW6 + ic * 6144 + (c << 2);
            #pragma unroll
            for (int j = 0; j < 6; j++) {
                float ul, uh;
                unpack2(ul, uh, u[j]);
                const ull us0 = dup2(ul);
                const ull us1 = dup2(uh);
                #pragma unroll
                for (int ocq = 0; ocq < 4; ocq++) {
                    ulonglong2 wv = *reinterpret_cast<const ulonglong2*>(
                        wbase + j * 1024 + ocq * 256);
                    ffma2(acc[0][ocq][0][j], wv.x, us0);
                    ffma2(acc[0][ocq][1][j], wv.y, us0);
                    ffma2(acc[1][ocq][0][j], wv.x, us1);
                    ffma2(acc[1][ocq][1][j], wv.y, us1);
                }
            }
        }

        // output transform y = AT acc6 + bias, then pool/leaky + folded dot
        float rs[2];
        #pragma unroll
        for (int s = 0; s < 2; s++) {
            ull r2 = pack2(bfc, 0.0f);
            #pragma unroll
            for (int ocq = 0; ocq < 4; ocq++) {
                ulonglong2 bv = *reinterpret_cast<const ulonglong2*>(
                    &sB2q[(ocq << 8) + (c << 2)]);
                #pragma unroll
                for (int h = 0; h < 2; h++) {
                    const ull bias2 = h ? bv.y : bv.x;
                    ull a0 = acc[s][ocq][h][0], a1 = acc[s][ocq][h][1],
                        a2 = acc[s][ocq][h][2], a3 = acc[s][ocq][h][3],
                        a4 = acc[s][ocq][h][4], a5 = acc[s][ocq][h][5];
                    ull s12 = add2(a1, a2), d12 = SUB2(a1, a2);
                    ull s34 = add2(a3, a4), d34 = SUB2(a3, a4);
                    ull y0 = add2(add2(a0, s12), add2(s34, bias2));
                    ull y1 = ffma2_3(c2p, d34, add2(d12, bias2));
                    ull y2 = ffma2_3(c4p, s34, add2(s12, bias2));
                    ull y3 = ffma2_3(c8p, d34, add2(add2(a5, bias2), d12));

                    float l0, h0, l1, h1, l2, h2, l3, h3;
                    unpack2(l0, h0, y0); unpack2(l1, h1, y1);
                    unpack2(l2, h2, y2); unpack2(l3, h3, y3);
                    const int oc0 = ocq * 4 + h * 2;
                    {
                        float M0 = fmaxf(l0, l1), M1 = fmaxf(l2, l3);
                        float f0 = fmaxf(M0, LEAK * M0), f1 = fmaxf(M1, LEAK * M1);
                        ull wf = *reinterpret_cast<const ull*>(&sWFq[(oc0 << 7) + (c << 1)]);
                        ffma2(r2, wf, pack2(f0, f1));
                    }
                    {
                        float M0 = fmaxf(h0, h1), M1 = fmaxf(h2, h3);
                        float f0 = fmaxf(M0, LEAK * M0), f1 = fmaxf(M1, LEAK * M1);
                        ull wf = *reinterpret_cast<const ull*>(&sWFq[((oc0 + 1) << 7) + (c << 1)]);
                        ffma2(r2, wf, pack2(f0, f1));
                    }
                }
            }
            float rl, rh;
            unpack2(rl, rh, r2);
            rs[s] = rl + rh;
        }

        // 64-channel reduction
        ull rp = pack2(rs[0], rs[1]);
        #pragma unroll
        for (int d = 16; d > 0; d >>= 1) {
            ull o2 = __shfl_down_sync(0xffffffffu, rp, d);
            asm("add.rn.f32x2 %0, %0, %1;" : "+l"(rp) : "l"(o2));
        }
        float* red = sRED + ((grp & 1) << 4);
        if ((tid & 31) == 0) *reinterpret_cast<ull*>(&red[2 * w]) = rp;
        __syncthreads();
        if (tid < 8) {
            int gg = tid & 3, hi = tid >> 2;
            out[grp * 8 + gg + 4 * hi] = red[4 * gg + hi] + red[4 * gg + 2 + hi];
        }
    }
    #undef SUB2
}

// ---------------------------------------------------------------------------
extern "C" void kernel_launch(void* const* d_in, const int* in_sizes, int n_in,
                              void* d_out, int out_size)
{
    const float* x   = (const float*)d_in[0];
    const float* w1  = (const float*)d_in[1];
    const float* b1  = (const float*)d_in[2];
    const float* w2  = (const float*)d_in[3];
    const float* b2  = (const float*)d_in[4];
    const float* fw1 = (const float*)d_in[5];
    const float* fb1 = (const float*)d_in[6];
    const float* fw2 = (const float*)d_in[7];
    const float* fb2 = (const float*)d_in[8];
    const float* fw3 = (const float*)d_in[9];
    const float* fb3 = (const float*)d_in[10];
    const float* dw1 = (const float*)d_in[11];
    const float* db1 = (const float*)d_in[12];
    const float* dw2 = (const float*)d_in[13];
    const float* db2 = (const float*)d_in[14];

    const int B = in_sizes[0] / 1024;
    const size_t smem = SM_FLOATS * sizeof(float);

    prep_kernel<<<64, 64>>>(fw1, fb1, fw2, fb2, fw3, fb3, dw1, db1, dw2, db2);
    prep_w6_kernel<<<192, 256>>>(w2);

    cudaFuncSetAttribute(main_kernel, cudaFuncAttributeMaxDynamicSharedMemorySize, (int)smem);
    main_kernel<<<148, THREADS, smem>>>(x, w1, b1, b2, (float*)d_out, B);
}

// round 7
// speedup vs baseline: 1.1834x; 1.1834x over previous
#include <cuda_runtime.h>

#define THREADS 256
#define LEAK 0.05f

// folded per-channel linear tail: Wfold[f][c] (f=0..31, c=0..63), bfold[c]
__device__ float g_Wfold[32 * 64];
__device__ float g_bfold[64];

// ---------------------------------------------------------------------------
// packed f32x2 helpers
// ---------------------------------------------------------------------------
typedef unsigned long long ull;
__device__ __forceinline__ ull pack2(float lo, float hi) {
    ull d; asm("mov.b64 %0, {%1, %2};" : "=l"(d) : "f"(lo), "f"(hi)); return d;
}
__device__ __forceinline__ ull dup2(float v) {
    ull d; asm("mov.b64 %0, {%1, %1};" : "=l"(d) : "f"(v)); return d;
}
__device__ __forceinline__ void ffma2(ull& acc, ull a, ull b) {
    asm("fma.rn.f32x2 %0, %1, %2, %0;" : "+l"(acc) : "l"(a), "l"(b));
}
__device__ __forceinline__ ull ffma2_3(ull a, ull b, ull c) {
    ull d; asm("fma.rn.f32x2 %0, %1, %2, %3;" : "=l"(d) : "l"(a), "l"(b), "l"(c)); return d;
}
__device__ __forceinline__ void unpack2(float& lo, float& hi, ull v) {
    asm("mov.b64 {%0, %1}, %2;" : "=f"(lo), "=f"(hi) : "l"(v));
}

// ---------------------------------------------------------------------------
// Prep (single kernel, 64 blocks x 256 threads, phase-parallel):
//   u[i]  = sum_j fw3[c,j] fw2[c,j,i]
//   t1[j] = fb2[c,j] + sum_i fw2[c,j,i] fb1[c,i]
//   gc    = sum_j dw2[j] dw1[j,c]
//   Wfold[f][c] = gc * sum_i u[i] fw1[c,i,f]
//   bfold[c]    = gc * (fb3[c] + sum_j fw3[c,j] t1[j]) + C/64
// ---------------------------------------------------------------------------
__global__ void prep_kernel(const float* __restrict__ fw1, const float* __restrict__ fb1,
                            const float* __restrict__ fw2, const float* __restrict__ fb2,
                            const float* __restrict__ fw3, const float* __restrict__ fb3,
                            const float* __restrict__ dw1, const float* __restrict__ db1,
                            const float* __restrict__ dw2, const float* __restrict__ db2)
{
    const int c = blockIdx.x;
    const int t = threadIdx.x;
    __shared__ float spA[4][64];   // u partials
    __shared__ float spB[4][32];   // t1 partials
    __shared__ float spC[4][32];   // Wfold partials
    __shared__ float su[64];
    __shared__ float st1[32];
    __shared__ float sgc;

    // phase 1: u partials — thread (p,i), 8 j's each
    {
        int i = t & 63, p = t >> 6;
        float s = 0.f;
        #pragma unroll
        for (int j = p * 8; j < p * 8 + 8; j++)
            s += fw3[c * 32 + j] * fw2[(c * 32 + j) * 64 + i];
        spA[p][i] = s;
    }
    __syncthreads();

    // phase 2: su reduce (t<64) | t1 partials (64<=t<192) | gc (t==255)
    if (t < 64) {
        su[t] = spA[0][t] + spA[1][t] + spA[2][t] + spA[3][t];
    } else if (t < 192) {
        int q = t - 64, j = q & 31, h = q >> 5;
        float a = 0.f;
        #pragma unroll
        for (int i = h * 16; i < h * 16 + 16; i++)
            a += fw2[(c * 32 + j) * 64 + i] * fb1[c * 64 + i];
        spB[h][j] = a;
    } else if (t == 255) {
        float gc = 0.f;
        #pragma unroll 4
        for (int j = 0; j < 32; j++) gc += dw2[j] * dw1[j * 64 + c];
        sgc = gc;
    }
    __syncthreads();

    // phase 3: Wfold partials (t<128, reads su) | st1 reduce (128<=t<160)
    if (t < 128) {
        int f = t & 31, h = t >> 5;
        float s = 0.f;
        #pragma unroll
        for (int i = h * 16; i < h * 16 + 16; i++)
            s += su[i] * fw1[(c * 64 + i) * 32 + f];
        spC[h][f] = s;
    } else if (t < 160) {
        int j = t - 128;
        st1[j] = spB[0][j] + spB[1][j] + spB[2][j] + spB[3][j] + fb2[c * 32 + j];
    }
    __syncthreads();

    // phase 4: final writes
    if (t < 32) {
        g_Wfold[t * 64 + c] = sgc * (spC[0][t] + spC[1][t] + spC[2][t] + spC[3][t]);
    } else if (t == 32) {
        float bias = fb3[c];
        #pragma unroll 4
        for (int j = 0; j < 32; j++) bias += fw3[c * 32 + j] * st1[j];
        float C = db2[0];
        #pragma unroll 4
        for (int j = 0; j < 32; j++) C += dw2[j] * db1[j];
        g_bfold[c] = sgc * bias + C * (1.0f / 64.0f);
    }
}

// ---------------------------------------------------------------------------
// Main kernel (R4 structure — proven at the FFMA2 rt-3 roofline):
// 256 threads, each thread handles TWO samples (s, s+4) of one channel.
// conv1 f32x2-packed across the sample pair; conv2 accumulators f32x2-packed
// across oc-pairs; conv2 bias vectors hoisted out of the grp loop.
//
// Shared float layout:
//   sW1q [8 o][64 c][4:(wa,wb,wc,b1)]          @0      (2048)
//   sW2q [96:(o,k,ocq)][64 c][4:oc%4]          @2048   (24576)
//   sB2q [4 ocq][64 c][4]                      @26624  (1024)
//   sWFq [16 oc][64 c][2:poolpos]              @27648  (2048)
//   sBF  [64]                                  @29696
//   sRED [2 buf][8 warps][2 samples]           @29760  (32)
// ---------------------------------------------------------------------------
#define SM_FLOATS 29792

__global__ __launch_bounds__(THREADS, 1)
void main_kernel(const float* __restrict__ x,
                 const float* __restrict__ w1, const float* __restrict__ b1,
                 const float* __restrict__ w2, const float* __restrict__ b2,
                 float* __restrict__ out, int B)
{
    extern __shared__ float sm[];
    float* sW1q = sm;
    float* sW2q = sm + 2048;
    float* sB2q = sm + 26624;
    float* sWFq = sm + 27648;
    float* sBF  = sm + 29696;
    float* sRED = sm + 29760;

    const int tid = threadIdx.x;

    // ---- stage weights (SoA transpose; one-time) ----
    for (int i = tid; i < 2048; i += THREADS) {           // sW1q
        int o = i >> 8, c = (i >> 2) & 63, j = i & 3;
        sW1q[i] = (j < 3) ? w1[c * 24 + o * 3 + j] : b1[c * 8 + o];
    }
    for (int i = tid; i < 24576; i += THREADS) {          // sW2q
        int row = i >> 8, c = (i >> 2) & 63, j = i & 3;
        int o = row / 12, k = (row / 4) % 3, ocq = row & 3;
        int oc = ocq * 4 + j;
        sW2q[i] = w2[((c * 16 + oc) * 8 + o) * 3 + k];
    }
    for (int i = tid; i < 1024; i += THREADS) {           // sB2q
        int ocq = i >> 8, c = (i >> 2) & 63, j = i & 3;
        sB2q[i] = b2[c * 16 + ocq * 4 + j];
    }
    for (int i = tid; i < 2048; i += THREADS) {           // sWFq
        int oc = i >> 7, c = (i >> 1) & 63, q = i & 1;
        sWFq[i] = g_Wfold[(oc * 2 + q) * 64 + c];
    }
    for (int i = tid; i < 64; i += THREADS) sBF[i] = g_bfold[i];
    __syncthreads();

    const int c = tid & 63;
    const int g = tid >> 6;   // 0..3
    const int w = tid >> 5;   // warp id 0..7
    const int NG = B >> 3;    // 8 samples per group iter (4 g-slots x 2)

    const float bfc = sBF[c];

    // loop-invariant conv2 bias vectors (hoisted)
    ull bias2[4][2];
    #pragma unroll
    for (int ocq = 0; ocq < 4; ocq++) {
        ulonglong2 bv = *reinterpret_cast<const ulonglong2*>(&sB2q[(ocq << 8) + (c << 2)]);
        bias2[ocq][0] = bv.x;
        bias2[ocq][1] = bv.y;
    }

    for (int grp = blockIdx.x; grp < NG; grp += gridDim.x) {
        const float* xp0 = x + (size_t)(grp * 8 + g) * 1024 + c;
        const float* xp1 = xp0 + 4 * 1024;

        // xr packed across the sample pair; positions 14,15 are dead
        // (m[6] feeds only conv2 position 4, trimmed by the pool).
        ull xr[14];
        #pragma unroll
        for (int t = 0; t < 14; t++) xr[t] = pack2(xp0[t * 64], xp1[t * 64]);

        // acc[s][ocq][pair][pos]
        ull acc[2][4][2][4];
        #pragma unroll
        for (int ocq = 0; ocq < 4; ocq++) {
            #pragma unroll
            for (int p = 0; p < 4; p++) {
                acc[0][ocq][0][p] = bias2[ocq][0]; acc[0][ocq][1][p] = bias2[ocq][1];
                acc[1][ocq][0][p] = bias2[ocq][0]; acc[1][ocq][1][p] = bias2[ocq][1];
            }
        }

        #pragma unroll
        for (int o = 0; o < 8; o++) {
            const float4 wv1 = *reinterpret_cast<const float4*>(&sW1q[(o << 8) + (c << 2)]);
            const ull wa2 = dup2(wv1.x);
            const ull wb2 = dup2(wv1.y);
            const ull wc2 = dup2(wv1.z);
            const ull bb2 = dup2(wv1.w);

            // conv1 packed over sample pair, then scalar pool+leaky per sample
            ull md[2][6];
            #pragma unroll
            for (int q = 0; q < 6; q++) {
                ull h0 = ffma2_3(wa2, xr[2 * q],
                         ffma2_3(wb2, xr[2 * q + 1],
                         ffma2_3(wc2, xr[2 * q + 2], bb2)));
                ull h1 = ffma2_3(wa2, xr[2 * q + 1],
                         ffma2_3(wb2, xr[2 * q + 2],
                         ffma2_3(wc2, xr[2 * q + 3], bb2)));
                float a0, a1, b0, b1;
                unpack2(a0, a1, h0);
                unpack2(b0, b1, h1);
                float M0 = fmaxf(a0, b0), M1 = fmaxf(a1, b1);
                md[0][q] = dup2(fmaxf(M0, LEAK * M0));   // leaky(max)=max(leaky)
                md[1][q] = dup2(fmaxf(M1, LEAK * M1));
            }

            #pragma unroll
            for (int k = 0; k < 3; k++) {
                #pragma unroll
                for (int ocq = 0; ocq < 4; ocq++) {
                    ulonglong2 wv = *reinterpret_cast<const ulonglong2*>(
                        &sW2q[(((o * 3 + k) << 2) + ocq) * 256 + (c << 2)]);
                    #pragma unroll
                    for (int p = 0; p < 4; p++) {
                        ffma2(acc[0][ocq][0][p], wv.x, md[0][p + k]);
                        ffma2(acc[0][ocq][1][p], wv.y, md[0][p + k]);
                        ffma2(acc[1][ocq][0][p], wv.x, md[1][p + k]);
                        ffma2(acc[1][ocq][1][p], wv.y, md[1][p + k]);
                    }
                }
            }
        }

        // epilogue per sample: pool+leaky on conv2, folded 32-dot (oc-paired)
        float rs[2];
        #pragma unroll
        for (int s = 0; s < 2; s++) {
            ull r2 = pack2(bfc, 0.0f);
            #pragma unroll
            for (int ocq = 0; ocq < 4; ocq++) {
                #pragma unroll
                for (int h = 0; h < 2; h++) {
                    float lo[4], hi[4];
                    #pragma unroll
                    for (int p = 0; p < 4; p++) unpack2(lo[p], hi[p], acc[s][ocq][h][p]);
                    const int oc0 = ocq * 4 + h * 2;
                    {
                        float M0 = fmaxf(lo[0], lo[1]), M1 = fmaxf(lo[2], lo[3]);
                        float f0 = fmaxf(M0, LEAK * M0), f1 = fmaxf(M1, LEAK * M1);
                        ull wf = *reinterpret_cast<const ull*>(&sWFq[(oc0 << 7) + (c << 1)]);
                        ffma2(r2, wf, pack2(f0, f1));
                    }
                    {
                        float M0 = fmaxf(hi[0], hi[1]), M1 = fmaxf(hi[2], hi[3]);
                        float f0 = fmaxf(M0, LEAK * M0), f1 = fmaxf(M1, LEAK * M1);
                        ull wf = *reinterpret_cast<const ull*>(&sWFq[((oc0 + 1) << 7) + (c << 1)]);
                        ffma2(r2, wf, pack2(f0, f1));
                    }
                }
            }
            float rl, rh;
            unpack2(rl, rh, r2);
            rs[s] = rl + rh;
        }

        // 64-channel reduction: packed shfl over 32 lanes, then warp-pairing.
        ull rp = pack2(rs[0], rs[1]);
        #pragma unroll
        for (int d = 16; d > 0; d >>= 1) {
            ull o2 = __shfl_down_sync(0xffffffffu, rp, d);
            asm("add.rn.f32x2 %0, %0, %1;" : "+l"(rp) : "l"(o2));
        }
        float* red = sRED + ((grp & 1) << 4);
        if ((tid & 31) == 0) *reinterpret_cast<ull*>(&red[2 * w]) = rp;
        __syncthreads();
        if (tid < 8) {
            int gg = tid & 3, hi = tid >> 2;            // hi: 0 -> sample g, 1 -> sample g+4
            out[grp * 8 + gg + 4 * hi] = red[4 * gg + hi] + red[4 * gg + 2 + hi];
        }
    }
}

// ---------------------------------------------------------------------------
extern "C" void kernel_launch(void* const* d_in, const int* in_sizes, int n_in,
                              void* d_out, int out_size)
{
    const float* x   = (const float*)d_in[0];
    const float* w1  = (const float*)d_in[1];
    const float* b1  = (const float*)d_in[2];
    const float* w2  = (const float*)d_in[3];
    const float* b2  = (const float*)d_in[4];
    const float* fw1 = (const float*)d_in[5];
    const float* fb1 = (const float*)d_in[6];
    const float* fw2 = (const float*)d_in[7];
    const float* fb2 = (const float*)d_in[8];
    const float* fw3 = (const float*)d_in[9];
    const float* fb3 = (const float*)d_in[10];
    const float* dw1 = (const float*)d_in[11];
    const float* db1 = (const float*)d_in[12];
    const float* dw2 = (const float*)d_in[13];
    const float* db2 = (const float*)d_in[14];

    const int B = in_sizes[0] / 1024;  // x is [B,1,16,8,8] = B*1024 floats
    const size_t smem = SM_FLOATS * sizeof(float);

    prep_kernel<<<64, 256>>>(fw1, fb1, fw2, fb2, fw3, fb3, dw1, db1, dw2, db2);

    cudaFuncSetAttribute(main_kernel, cudaFuncAttributeMaxDynamicSharedMemorySize, (int)smem);
    main_kernel<<<148, THREADS, smem>>>(x, w1, b1, w2, b2, (float*)d_out, B);
}